// round 1
// baseline (speedup 1.0000x reference)
#include <cuda_runtime.h>
#include <math.h>

#define LEAK 0.01f

// ---------------- scratch (device globals; no allocation allowed) -----------
__device__ float g_seq[4096 * 180];   // [B, 18, 10] flow-LSTM input
__device__ float g_fv [4096 * 10];    // [B, 10] flow vectors = [64,64,10]
__device__ float g_tv [64 * 10];      // [64, 10] trace vectors

// ---------------- helpers ---------------------------------------------------
__device__ __forceinline__ float lrelu(float x) { return x > 0.f ? x : LEAK * x; }

// overflow-safe fast sigmoid/tanh (gate pre-activations can be O(100+))
__device__ __forceinline__ float sigm(float x) {
    return __fdividef(1.f, 1.f + __expf(-x));   // x<<0: 1/(1+inf)=0 ; x>>0: 1/(1+0)=1
}
__device__ __forceinline__ float tanh_s(float x) {
    float e = __expf(-2.f * fabsf(x));          // always in (0,1]; no overflow
    float r = __fdividef(1.f - e, 1.f + e);
    return copysignf(r, x);
}

// ---------------- stage 1: conv+lrelu+pool x3, one block per sequence -------
__global__ __launch_bounds__(160) void conv_stage(
    const float* __restrict__ din,
    const float* __restrict__ W1, const float* __restrict__ B1,
    const float* __restrict__ W2, const float* __restrict__ B2,
    const float* __restrict__ W3, const float* __restrict__ B3)
{
    __shared__ float xs[3 * 512];
    __shared__ float p1[10 * 170];
    __shared__ float p2[5 * 56];
    __shared__ float w1s[150]; __shared__ float b1s[10];
    __shared__ float w2s[250]; __shared__ float b2s[5];
    __shared__ float w3s[250]; __shared__ float b3s[10];

    const int tid = threadIdx.x;
    const int b   = blockIdx.x;

    // load input [512,3] -> smem transposed [3][512] (coalesced global reads)
    const float* xin = din + (size_t)b * 1536;
    for (int i = tid; i < 1536; i += 160) xs[(i % 3) * 512 + i / 3] = xin[i];
    if (tid < 150) w1s[tid] = W1[tid];
    if (tid < 10)  b1s[tid] = B1[tid];
    for (int i = tid; i < 250; i += 160) w2s[i] = W2[i];
    if (tid < 5)   b2s[tid] = B2[tid];
    for (int i = tid; i < 250; i += 160) w3s[i] = W3[i];
    if (tid < 10)  b3s[tid] = B3[tid];
    __syncthreads();

    // conv1 (Cin=3,K=5,L=508) + pool3(pad1) -> p1[10][170]
    {
        const int co = tid >> 4, jb = tid & 15;   // 10 x 16 threads
        float w[15];
        #pragma unroll
        for (int i = 0; i < 15; i++) w[i] = w1s[co * 15 + i];
        const float bv = b1s[co];
        for (int j = jb; j < 170; j += 16) {
            const int c0 = 3 * j - 1;
            float m = -1e30f;
            #pragma unroll
            for (int dc = 0; dc < 3; dc++) {
                const int l = c0 + dc;
                if (l >= 0 && l < 508) {
                    float s = bv;
                    #pragma unroll
                    for (int ci = 0; ci < 3; ci++)
                        #pragma unroll
                        for (int k = 0; k < 5; k++)
                            s += xs[ci * 512 + l + k] * w[ci * 5 + k];
                    m = fmaxf(m, s);
                }
            }
            p1[co * 170 + j] = lrelu(m);   // lrelu monotone => pool-then-lrelu OK
        }
    }
    __syncthreads();

    // conv2 (Cin=10,K=5,L=166) + pool -> p2[5][56]
    {
        const int co = tid >> 5, jb = tid & 31;   // 5 x 32 threads
        float w[50];
        #pragma unroll
        for (int i = 0; i < 50; i++) w[i] = w2s[co * 50 + i];
        const float bv = b2s[co];
        for (int j = jb; j < 56; j += 32) {
            const int c0 = 3 * j - 1;
            float m = -1e30f;
            #pragma unroll
            for (int dc = 0; dc < 3; dc++) {
                const int l = c0 + dc;
                if (l >= 0 && l < 166) {
                    float s = bv;
                    #pragma unroll
                    for (int ci = 0; ci < 10; ci++)
                        #pragma unroll
                        for (int k = 0; k < 5; k++)
                            s += p1[ci * 170 + l + k] * w[ci * 5 + k];
                    m = fmaxf(m, s);
                }
            }
            p2[co * 56 + j] = lrelu(m);
        }
    }
    __syncthreads();

    // conv3 (Cin=5,K=5,L=52) + pool -> g_seq[b][t][co], t in [0,18)
    {
        const int co = tid >> 4, jb = tid & 15;   // 10 x 16 threads
        float w[25];
        #pragma unroll
        for (int i = 0; i < 25; i++) w[i] = w3s[co * 25 + i];
        const float bv = b3s[co];
        for (int t = jb; t < 18; t += 16) {
            const int c0 = 3 * t - 1;
            float m = -1e30f;
            #pragma unroll
            for (int dc = 0; dc < 3; dc++) {
                const int l = c0 + dc;
                if (l >= 0 && l < 52) {
                    float s = bv;
                    #pragma unroll
                    for (int ci = 0; ci < 5; ci++)
                        #pragma unroll
                        for (int k = 0; k < 5; k++)
                            s += p2[ci * 56 + l + k] * w[ci * 5 + k];
                    m = fmaxf(m, s);
                }
            }
            g_seq[(size_t)b * 180 + t * 10 + co] = lrelu(m);
        }
    }
}

// ---------------- stage 2: flow LSTM (3 layers, T=18, H=10) -----------------
// 32 batches per block; warp w handles hidden unit u=w for all 32 batches
// (weight loads are warp-uniform; lane = batch index).
__global__ __launch_bounds__(320) void flow_lstm(
    const float* __restrict__ Wih, const float* __restrict__ Whh,
    const float* __restrict__ Bv)
{
    __shared__ float bufA[32 * 180];
    __shared__ float bufB[32 * 180];
    __shared__ float hs[320];          // [bi][u]

    const int tid = threadIdx.x;
    const int u  = tid >> 5;           // 0..9  (warp id)
    const int bi = tid & 31;           // 0..31 (lane)
    const int b0 = blockIdx.x * 32;

    for (int i = tid; i < 5760; i += 320) bufA[i] = g_seq[(size_t)b0 * 180 + i];

    float acc = 0.f;
    float* inb  = bufA;
    float* outb = bufB;

    for (int l = 0; l < 3; l++) {
        const float* wihL = Wih + l * 400;
        const float* whhL = Whh + l * 400;
        const float* bbL  = Bv  + l * 40;
        float wx[40], wh[40], bg[4];
        #pragma unroll
        for (int g = 0; g < 4; g++) {
            const int row = g * 10 + u;
            #pragma unroll
            for (int k = 0; k < 10; k++) {
                wx[g * 10 + k] = wihL[row * 10 + k];
                wh[g * 10 + k] = whhL[row * 10 + k];
            }
            bg[g] = bbL[row];
        }
        float c = 0.f, h = 0.f;
        hs[bi * 10 + u] = 0.f;
        __syncthreads();               // also covers bufA load on l==0

        for (int t = 0; t < 18; t++) {
            const float* xp = inb + bi * 180 + t * 10;
            float g0 = bg[0], g1 = bg[1], g2 = bg[2], g3 = bg[3];
            #pragma unroll
            for (int k = 0; k < 10; k++) {
                const float xv = xp[k];
                const float hv = hs[bi * 10 + k];
                g0 += xv * wx[k]      + hv * wh[k];
                g1 += xv * wx[10 + k] + hv * wh[10 + k];
                g2 += xv * wx[20 + k] + hv * wh[20 + k];
                g3 += xv * wx[30 + k] + hv * wh[30 + k];
            }
            const float ig = sigm(g0), fg = sigm(g1);
            const float gg = tanh_s(g2), og = sigm(g3);
            c = fg * c + ig * gg;
            h = og * tanh_s(c);
            __syncthreads();
            hs[bi * 10 + u] = h;
            outb[bi * 180 + t * 10 + u] = h;
            __syncthreads();
        }
        if (l >= 1) acc += h;          // h_n[-1] + h_n[-2]
        float* tmp = inb; inb = outb; outb = tmp;
    }
    g_fv[(size_t)(b0 + bi) * 10 + u] = acc;
}

// ---------------- stage 3: trace LSTM (batch=64 over T, time=64 over F) -----
// 8 batches per block x 10 units = 80 threads, 8 blocks.
__global__ __launch_bounds__(80) void trace_lstm(
    const float* __restrict__ Wih, const float* __restrict__ Whh,
    const float* __restrict__ Bv)
{
    __shared__ float bufA[8 * 640];
    __shared__ float bufB[8 * 640];
    __shared__ float hs[80];

    const int tid = threadIdx.x;
    const int bi = tid / 10;
    const int u  = tid - bi * 10;
    const int b0 = blockIdx.x * 8;

    for (int i = tid; i < 5120; i += 80) bufA[i] = g_fv[(size_t)b0 * 640 + i];

    float acc = 0.f;
    float* inb  = bufA;
    float* outb = bufB;

    for (int l = 0; l < 3; l++) {
        const float* wihL = Wih + l * 400;
        const float* whhL = Whh + l * 400;
        const float* bbL  = Bv  + l * 40;
        float wx[40], wh[40], bg[4];
        #pragma unroll
        for (int g = 0; g < 4; g++) {
            const int row = g * 10 + u;
            #pragma unroll
            for (int k = 0; k < 10; k++) {
                wx[g * 10 + k] = wihL[row * 10 + k];
                wh[g * 10 + k] = whhL[row * 10 + k];
            }
            bg[g] = bbL[row];
        }
        float c = 0.f, h = 0.f;
        hs[tid] = 0.f;                 // hs[bi*10+u] == hs[tid] with this mapping
        __syncthreads();

        for (int t = 0; t < 64; t++) {
            const float* xp = inb + bi * 640 + t * 10;
            float g0 = bg[0], g1 = bg[1], g2 = bg[2], g3 = bg[3];
            #pragma unroll
            for (int k = 0; k < 10; k++) {
                const float xv = xp[k];
                const float hv = hs[bi * 10 + k];
                g0 += xv * wx[k]      + hv * wh[k];
                g1 += xv * wx[10 + k] + hv * wh[10 + k];
                g2 += xv * wx[20 + k] + hv * wh[20 + k];
                g3 += xv * wx[30 + k] + hv * wh[30 + k];
            }
            const float ig = sigm(g0), fg = sigm(g1);
            const float gg = tanh_s(g2), og = sigm(g3);
            c = fg * c + ig * gg;
            h = og * tanh_s(c);
            __syncthreads();
            hs[bi * 10 + u] = h;
            outb[bi * 640 + t * 10 + u] = h;
            __syncthreads();
        }
        if (l >= 1) acc += h;
        float* tmp = inb; inb = outb; outb = tmp;
    }
    g_tv[(size_t)(b0 + bi) * 10 + u] = acc;
}

// ---------------- stage 4: MLP head, one block per output row ---------------
__global__ __launch_bounds__(256) void mlp_kernel(
    const float* __restrict__ L1W, const float* __restrict__ L1b,
    const float* __restrict__ L2W, const float* __restrict__ L2b,
    const float* __restrict__ L3W, const float* __restrict__ L3b,
    const float* __restrict__ L4W, const float* __restrict__ L4b,
    float* __restrict__ out)
{
    __shared__ float x0[10];
    __shared__ float h1[128];
    __shared__ float h2[256];
    __shared__ float h3[64];

    const int t   = blockIdx.x;
    const int tid = threadIdx.x;

    if (tid < 10) x0[tid] = g_tv[t * 10 + tid];
    __syncthreads();

    if (tid < 128) {
        float s = L1b[tid];
        #pragma unroll
        for (int k = 0; k < 10; k++) s += x0[k] * L1W[tid * 10 + k];
        h1[tid] = lrelu(s);
    }
    __syncthreads();

    {
        float s = L2b[tid];
        #pragma unroll 8
        for (int k = 0; k < 128; k++) s += h1[k] * L2W[tid * 128 + k];
        h2[tid] = lrelu(s);
    }
    __syncthreads();

    if (tid < 64) {
        float s = L3b[tid];
        #pragma unroll 8
        for (int k = 0; k < 256; k++) s += h2[k] * L3W[tid * 256 + k];
        h3[tid] = lrelu(s);
    }
    __syncthreads();

    if (tid < 7) {
        float s = L4b[tid];
        #pragma unroll
        for (int k = 0; k < 64; k++) s += h3[k] * L4W[tid * 64 + k];
        out[t * 7 + tid] = s;
    }
}

// ---------------- launch ----------------------------------------------------
extern "C" void kernel_launch(void* const* d_in, const int* in_sizes, int n_in,
                              void* d_out, int out_size)
{
    const float* din  = (const float*)d_in[0];
    const float* W1   = (const float*)d_in[1];
    const float* b1   = (const float*)d_in[2];
    const float* W2   = (const float*)d_in[3];
    const float* b2   = (const float*)d_in[4];
    const float* W3   = (const float*)d_in[5];
    const float* b3   = (const float*)d_in[6];
    const float* fWih = (const float*)d_in[7];
    const float* fWhh = (const float*)d_in[8];
    const float* fb   = (const float*)d_in[9];
    const float* tWih = (const float*)d_in[10];
    const float* tWhh = (const float*)d_in[11];
    const float* tb   = (const float*)d_in[12];
    const float* L1W  = (const float*)d_in[13];
    const float* L1b  = (const float*)d_in[14];
    const float* L2W  = (const float*)d_in[15];
    const float* L2b  = (const float*)d_in[16];
    const float* L3W  = (const float*)d_in[17];
    const float* L3b  = (const float*)d_in[18];
    const float* L4W  = (const float*)d_in[19];
    const float* L4b  = (const float*)d_in[20];

    conv_stage<<<4096, 160>>>(din, W1, b1, W2, b2, W3, b3);
    flow_lstm <<<128, 320>>>(fWih, fWhh, fb);
    trace_lstm<<<8, 80>>>(tWih, tWhh, tb);
    mlp_kernel<<<64, 256>>>(L1W, L1b, L2W, L2b, L3W, L3b, L4W, L4b,
                            (float*)d_out);
}

// round 2
// speedup vs baseline: 1.0184x; 1.0184x over previous
#include <cuda_runtime.h>
#include <math.h>

#define LEAK 0.01f

// ---------------- scratch (device globals; no allocation allowed) -----------
__device__ float g_seq[4096 * 180];   // [B, 18, 10] flow-LSTM input
__device__ float g_fv [4096 * 10];    // [B, 10] flow vectors = [64,64,10]
__device__ float g_tv [64 * 10];      // [64, 10] trace vectors

// ---------------- helpers ---------------------------------------------------
__device__ __forceinline__ float lrelu(float x) { return x > 0.f ? x : LEAK * x; }

// overflow-safe fast sigmoid; tanh(x) = 2*sigm(2x)-1 (also overflow-safe)
__device__ __forceinline__ float sigm(float x) {
    return __fdividef(1.f, 1.f + __expf(-x));
}
__device__ __forceinline__ float tanh_s(float x) {
    return 2.f * sigm(2.f * x) - 1.f;
}

// fused conv(K=5)+pool3(pad1)+lrelu for one pooled output j.
// xs: smem input [CIN][STRIDE]; w: per-thread reg weights [CIN*5].
// VALIDL = conv output length; MAXI = STRIDE-1; last = last pooled index.
template<int CIN, int STRIDE, int VALIDL, int MAXI>
__device__ __forceinline__ float conv_pool(const float* __restrict__ xs,
                                           const float* __restrict__ w,
                                           float bv, int j, int last)
{
    const int c0 = 3 * j - 1;
    float s0 = bv, s1 = bv, s2 = bv;
    if (j > 0 && j < last) {               // interior: unconditional loads
        #pragma unroll
        for (int ci = 0; ci < CIN; ci++) {
            float x[7];
            #pragma unroll
            for (int i = 0; i < 7; i++) x[i] = xs[ci * STRIDE + c0 + i];
            #pragma unroll
            for (int k = 0; k < 5; k++) {
                const float wv = w[ci * 5 + k];
                s0 += x[k]     * wv;
                s1 += x[k + 1] * wv;
                s2 += x[k + 2] * wv;
            }
        }
    } else {                               // edges: clamped loads
        #pragma unroll
        for (int ci = 0; ci < CIN; ci++) {
            float x[7];
            #pragma unroll
            for (int i = 0; i < 7; i++) {
                int idx = c0 + i;
                idx = idx < 0 ? 0 : (idx > MAXI ? MAXI : idx);
                x[i] = xs[ci * STRIDE + idx];
            }
            #pragma unroll
            for (int k = 0; k < 5; k++) {
                const float wv = w[ci * 5 + k];
                s0 += x[k]     * wv;
                s1 += x[k + 1] * wv;
                s2 += x[k + 2] * wv;
            }
        }
    }
    float m = s1;                           // position c0+1 = 3j always valid
    if (c0 >= 0)          m = fmaxf(m, s0);
    if (c0 + 2 < VALIDL)  m = fmaxf(m, s2);
    return lrelu(m);                        // lrelu monotone => pool-then-lrelu
}

// ---------------- stage 1: conv+lrelu+pool x3, one block per sequence -------
__global__ __launch_bounds__(160) void conv_stage(
    const float* __restrict__ din,
    const float* __restrict__ W1, const float* __restrict__ B1,
    const float* __restrict__ W2, const float* __restrict__ B2,
    const float* __restrict__ W3, const float* __restrict__ B3)
{
    __shared__ float xs[3 * 512];
    __shared__ float p1[10 * 170];
    __shared__ float p2[5 * 56];
    __shared__ float w1s[150]; __shared__ float b1s[10];
    __shared__ float w2s[250]; __shared__ float b2s[5];
    __shared__ float w3s[250]; __shared__ float b3s[10];

    const int tid = threadIdx.x;
    const int b   = blockIdx.x;

    const float* xin = din + (size_t)b * 1536;
    for (int i = tid; i < 1536; i += 160) xs[(i % 3) * 512 + i / 3] = xin[i];
    if (tid < 150) w1s[tid] = W1[tid];
    if (tid < 10)  b1s[tid] = B1[tid];
    for (int i = tid; i < 250; i += 160) w2s[i] = W2[i];
    if (tid < 5)   b2s[tid] = B2[tid];
    for (int i = tid; i < 250; i += 160) w3s[i] = W3[i];
    if (tid < 10)  b3s[tid] = B3[tid];
    __syncthreads();

    // conv1: Cin=3, L=508 -> p1[10][170]; contiguous j-chunks per thread
    {
        const int co = tid >> 4, jb = tid & 15;    // 10 x 16
        float w[15];
        #pragma unroll
        for (int i = 0; i < 15; i++) w[i] = w1s[co * 15 + i];
        const float bv = b1s[co];
        const int j0 = jb * 11;
        const int je = (j0 + 11 < 170) ? j0 + 11 : 170;
        for (int j = j0; j < je; j++)
            p1[co * 170 + j] = conv_pool<3, 512, 508, 511>(xs, w, bv, j, 169);
    }
    __syncthreads();

    // conv2: Cin=10, L=166 -> p2[5][56]
    {
        const int co = tid >> 5, jb = tid & 31;    // 5 x 32
        float w[50];
        #pragma unroll
        for (int i = 0; i < 50; i++) w[i] = w2s[co * 50 + i];
        const float bv = b2s[co];
        const int j0 = jb * 2;
        const int je = (j0 + 2 < 56) ? j0 + 2 : 56;
        for (int j = j0; j < je; j++)
            p2[co * 56 + j] = conv_pool<10, 170, 166, 169>(p1, w, bv, j, 55);
    }
    __syncthreads();

    // conv3: Cin=5, L=52 -> g_seq[b][t][co], t in [0,18)
    {
        const int co = tid >> 4, jb = tid & 15;    // 10 x 16
        float w[25];
        #pragma unroll
        for (int i = 0; i < 25; i++) w[i] = w3s[co * 25 + i];
        const float bv = b3s[co];
        const int t0 = jb * 2;
        const int te = (t0 + 2 < 18) ? t0 + 2 : 18;
        for (int t = t0; t < te; t++)
            g_seq[(size_t)b * 180 + t * 10 + co] =
                conv_pool<5, 56, 52, 55>(p2, w, bv, t, 17);
    }
}

// ---------------- stage 2: flow LSTM (3 layers, T=18, H=10) -----------------
// 32 batches/block; warp u handles hidden unit u for 32 batches (lane = batch).
// Single in-place sequence buffer (write slot t-1 during step t), double-
// buffered h -> ONE __syncthreads per step.
__global__ __launch_bounds__(320) void flow_lstm(
    const float* __restrict__ Wih, const float* __restrict__ Whh,
    const float* __restrict__ Bv)
{
    __shared__ __align__(16) float buf[32 * 180];
    __shared__ __align__(16) float hs[2][320];

    const int tid = threadIdx.x;
    const int u  = tid >> 5;           // 0..9
    const int bi = tid & 31;           // 0..31
    const int b0 = blockIdx.x * 32;

    for (int i = tid; i < 5760; i += 320) buf[i] = g_seq[(size_t)b0 * 180 + i];

    float acc = 0.f;

    for (int l = 0; l < 3; l++) {
        const float* wihL = Wih + l * 400;
        const float* whhL = Whh + l * 400;
        const float* bbL  = Bv  + l * 40;
        float wx[40], wh[40], bg[4];
        #pragma unroll
        for (int g = 0; g < 4; g++) {
            const int row = g * 10 + u;
            #pragma unroll
            for (int k = 0; k < 10; k++) {
                wx[g * 10 + k] = wihL[row * 10 + k];
                wh[g * 10 + k] = whhL[row * 10 + k];
            }
            bg[g] = bbL[row];
        }
        float c = 0.f, h = 0.f;
        int cur = 0;
        hs[0][bi * 10 + u] = 0.f;
        __syncthreads();   // covers buf fill / prev-layer final write / hs init

        for (int t = 0; t < 18; t++) {
            if (t > 0) buf[bi * 180 + (t - 1) * 10 + u] = h;  // deferred output
            const float2* xp2 = (const float2*)(buf + bi * 180 + t * 10);
            const float2* hp2 = (const float2*)(&hs[cur][bi * 10]);
            float g0a = bg[0], g1a = bg[1], g2a = bg[2], g3a = bg[3];
            float g0b = 0.f, g1b = 0.f, g2b = 0.f, g3b = 0.f;
            #pragma unroll
            for (int k2 = 0; k2 < 5; k2++) {
                const float2 xv = xp2[k2];
                const float2 hv = hp2[k2];
                g0a += xv.x * wx[2*k2]      + hv.x * wh[2*k2];
                g0b += xv.y * wx[2*k2 + 1]  + hv.y * wh[2*k2 + 1];
                g1a += xv.x * wx[10+2*k2]   + hv.x * wh[10+2*k2];
                g1b += xv.y * wx[11+2*k2]   + hv.y * wh[11+2*k2];
                g2a += xv.x * wx[20+2*k2]   + hv.x * wh[20+2*k2];
                g2b += xv.y * wx[21+2*k2]   + hv.y * wh[21+2*k2];
                g3a += xv.x * wx[30+2*k2]   + hv.x * wh[30+2*k2];
                g3b += xv.y * wx[31+2*k2]   + hv.y * wh[31+2*k2];
            }
            const float gi = sigm(g0a + g0b), gf = sigm(g1a + g1b);
            const float gg = tanh_s(g2a + g2b), go = sigm(g3a + g3b);
            c = gf * c + gi * gg;
            h = go * tanh_s(c);
            hs[cur ^ 1][bi * 10 + u] = h;
            __syncthreads();
            cur ^= 1;
        }
        buf[bi * 180 + 170 + u] = h;   // slot t=17
        if (l >= 1) acc += h;          // h_n[-1] + h_n[-2]
    }
    g_fv[(size_t)(b0 + bi) * 10 + u] = acc;
}

// ---------------- stage 3: trace LSTM — one warp per trace, zero bar.sync ---
// lane = (half, u): half in {0,1} splits the k-dim; h exchanged via shfl.
// Activations split across halves; tanh via 2*sigm(2x)-1 (6 MUFU-pairs/step).
__global__ __launch_bounds__(32) void trace_lstm(
    const float* __restrict__ Wih, const float* __restrict__ Whh,
    const float* __restrict__ Bv)
{
    __shared__ __align__(16) float bufA[640];
    __shared__ __align__(16) float bufB[640];

    const int lane = threadIdx.x;
    const int b    = blockIdx.x;
    int half = lane / 10; if (half > 1) half = 1;   // lanes 20..31 mirror half1
    const int u = lane % 10;

    for (int i = lane; i < 640; i += 32) bufA[i] = g_fv[(size_t)b * 640 + i];
    __syncwarp();

    float acc = 0.f;
    float* inb  = bufA;
    float* outb = bufB;

    for (int l = 0; l < 3; l++) {
        const float* wihL = Wih + l * 400;
        const float* whhL = Whh + l * 400;
        const float* bbL  = Bv  + l * 40;
        float wx[4][5], wh[4][5], bg[4];
        #pragma unroll
        for (int g = 0; g < 4; g++) {
            const int row = g * 10 + u;
            #pragma unroll
            for (int j = 0; j < 5; j++) {
                wx[g][j] = wihL[row * 10 + half * 5 + j];
                wh[g][j] = whhL[row * 10 + half * 5 + j];
            }
            bg[g] = (half == 0) ? bbL[row] : 0.f;
        }
        float c = 0.f, h = 0.f;

        for (int t = 0; t < 64; t++) {
            const float* xp = inb + t * 10 + half * 5;
            float p0 = bg[0], p1 = bg[1], p2 = bg[2], p3 = bg[3];
            #pragma unroll
            for (int j = 0; j < 5; j++) {
                const float xv = xp[j];
                const float hv = __shfl_sync(0xFFFFFFFFu, h, half * 5 + j);
                p0 += xv * wx[0][j] + hv * wh[0][j];
                p1 += xv * wx[1][j] + hv * wh[1][j];
                p2 += xv * wx[2][j] + hv * wh[2][j];
                p3 += xv * wx[3][j] + hv * wh[3][j];
            }
            // combine the two k-halves (both halves end with full sums)
            const float q0 = __shfl_down_sync(0xFFFFFFFFu, p0, 10);
            const float r0 = __shfl_up_sync  (0xFFFFFFFFu, p0, 10);
            const float q1 = __shfl_down_sync(0xFFFFFFFFu, p1, 10);
            const float r1 = __shfl_up_sync  (0xFFFFFFFFu, p1, 10);
            const float q2 = __shfl_down_sync(0xFFFFFFFFu, p2, 10);
            const float r2 = __shfl_up_sync  (0xFFFFFFFFu, p2, 10);
            const float q3 = __shfl_down_sync(0xFFFFFFFFu, p3, 10);
            const float r3 = __shfl_up_sync  (0xFFFFFFFFu, p3, 10);
            const float fi = p0 + (half == 0 ? q0 : r0);
            const float ff = p1 + (half == 0 ? q1 : r1);
            const float fg = p2 + (half == 0 ? q2 : r2);
            const float fo = p3 + (half == 0 ? q3 : r3);
            // half0 activates i and g(tanh); half1 activates f and o
            const float a1 = (half == 0) ? fi : ff;
            const float a2 = (half == 0) ? fg : fo;
            const float v1 = sigm(a1);
            const float v2r = sigm((half == 0) ? 2.f * a2 : a2);
            const float v2 = (half == 0) ? 2.f * v2r - 1.f : v2r;
            const float ihat = __shfl_sync(0xFFFFFFFFu, v1, u);
            const float fhat = __shfl_sync(0xFFFFFFFFu, v1, 10 + u);
            const float ghat = __shfl_sync(0xFFFFFFFFu, v2, u);
            const float ohat = __shfl_sync(0xFFFFFFFFu, v2, 10 + u);
            c = fhat * c + ihat * ghat;
            const float tc = 2.f * sigm(2.f * c) - 1.f;
            h = ohat * tc;
            if (lane < 10) outb[t * 10 + u] = h;
        }
        __syncwarp();
        if (l >= 1) acc += h;
        float* tmp = inb; inb = outb; outb = tmp;
    }
    if (lane < 10) g_tv[(size_t)b * 10 + u] = acc;
}

// ---------------- stage 4: MLP head — float4 loads + k-split + shfl reduce --
__global__ __launch_bounds__(512) void mlp_kernel(
    const float* __restrict__ L1W, const float* __restrict__ L1b,
    const float* __restrict__ L2W, const float* __restrict__ L2b,
    const float* __restrict__ L3W, const float* __restrict__ L3b,
    const float* __restrict__ L4W, const float* __restrict__ L4b,
    float* __restrict__ out)
{
    __shared__ __align__(16) float x0[16];
    __shared__ __align__(16) float h1[128];
    __shared__ __align__(16) float h2[256];
    __shared__ __align__(16) float h3[64];

    const int t   = blockIdx.x;
    const int tid = threadIdx.x;

    if (tid < 10) x0[tid] = g_tv[t * 10 + tid];
    __syncthreads();

    if (tid < 128) {
        float s = L1b[tid];
        #pragma unroll
        for (int k = 0; k < 10; k++) s += x0[k] * L1W[tid * 10 + k];
        h1[tid] = lrelu(s);
    }
    __syncthreads();

    // L2: 256 outputs, 2-way k-split, float4 loads
    {
        const int o = tid >> 1, p = tid & 1;
        const float4* wp = (const float4*)(L2W + o * 128 + p * 64);
        const float4* hp = (const float4*)(h1 + p * 64);
        float sa = 0.f, sb = 0.f;
        #pragma unroll
        for (int i = 0; i < 16; i += 2) {
            const float4 w0 = wp[i],   v0 = hp[i];
            const float4 w1 = wp[i+1], v1 = hp[i+1];
            sa += w0.x*v0.x + w0.y*v0.y + w0.z*v0.z + w0.w*v0.w;
            sb += w1.x*v1.x + w1.y*v1.y + w1.z*v1.z + w1.w*v1.w;
        }
        float s = sa + sb;
        s += __shfl_xor_sync(0xFFFFFFFFu, s, 1);
        if (p == 0) h2[o] = lrelu(s + L2b[o]);
    }
    __syncthreads();

    // L3: 64 outputs, 8-way k-split
    {
        const int o = tid >> 3, p = tid & 7;
        const float4* wp = (const float4*)(L3W + o * 256 + p * 32);
        const float4* hp = (const float4*)(h2 + p * 32);
        float sa = 0.f, sb = 0.f;
        #pragma unroll
        for (int i = 0; i < 8; i += 2) {
            const float4 w0 = wp[i],   v0 = hp[i];
            const float4 w1 = wp[i+1], v1 = hp[i+1];
            sa += w0.x*v0.x + w0.y*v0.y + w0.z*v0.z + w0.w*v0.w;
            sb += w1.x*v1.x + w1.y*v1.y + w1.z*v1.z + w1.w*v1.w;
        }
        float s = sa + sb;
        s += __shfl_xor_sync(0xFFFFFFFFu, s, 4);
        s += __shfl_xor_sync(0xFFFFFFFFu, s, 2);
        s += __shfl_xor_sync(0xFFFFFFFFu, s, 1);
        if (p == 0) h3[o] = lrelu(s + L3b[o]);
    }
    __syncthreads();

    // L4: 7 outputs, warp per output
    {
        const int w = tid >> 5, lane = tid & 31;
        if (w < 7) {
            float s = h3[lane] * L4W[w * 64 + lane]
                    + h3[lane + 32] * L4W[w * 64 + lane + 32];
            s += __shfl_xor_sync(0xFFFFFFFFu, s, 16);
            s += __shfl_xor_sync(0xFFFFFFFFu, s, 8);
            s += __shfl_xor_sync(0xFFFFFFFFu, s, 4);
            s += __shfl_xor_sync(0xFFFFFFFFu, s, 2);
            s += __shfl_xor_sync(0xFFFFFFFFu, s, 1);
            if (lane == 0) out[t * 7 + w] = s + L4b[w];
        }
    }
}

// ---------------- launch ----------------------------------------------------
extern "C" void kernel_launch(void* const* d_in, const int* in_sizes, int n_in,
                              void* d_out, int out_size)
{
    const float* din  = (const float*)d_in[0];
    const float* W1   = (const float*)d_in[1];
    const float* b1   = (const float*)d_in[2];
    const float* W2   = (const float*)d_in[3];
    const float* b2   = (const float*)d_in[4];
    const float* W3   = (const float*)d_in[5];
    const float* b3   = (const float*)d_in[6];
    const float* fWih = (const float*)d_in[7];
    const float* fWhh = (const float*)d_in[8];
    const float* fb   = (const float*)d_in[9];
    const float* tWih = (const float*)d_in[10];
    const float* tWhh = (const float*)d_in[11];
    const float* tb   = (const float*)d_in[12];
    const float* L1W  = (const float*)d_in[13];
    const float* L1b  = (const float*)d_in[14];
    const float* L2W  = (const float*)d_in[15];
    const float* L2b  = (const float*)d_in[16];
    const float* L3W  = (const float*)d_in[17];
    const float* L3b  = (const float*)d_in[18];
    const float* L4W  = (const float*)d_in[19];
    const float* L4b  = (const float*)d_in[20];

    conv_stage<<<4096, 160>>>(din, W1, b1, W2, b2, W3, b3);
    flow_lstm <<<128, 320>>>(fWih, fWhh, fb);
    trace_lstm<<<64, 32>>>(tWih, tWhh, tb);
    mlp_kernel<<<64, 512>>>(L1W, L1b, L2W, L2b, L3W, L3b, L4W, L4b,
                            (float*)d_out);
}

// round 3
// speedup vs baseline: 1.1173x; 1.0971x over previous
#include <cuda_runtime.h>
#include <math.h>

#define LEAK 0.01f

typedef unsigned long long u64;

// ---------------- scratch (device globals; no allocation allowed) -----------
__device__ float g_seq[4096 * 180];   // [B, 18, 10] flow-LSTM input
__device__ float g_fv [4096 * 10];    // [B, 10] flow vectors = [64,64,10]
__device__ float g_tv [64 * 10];      // [64, 10] trace vectors

// ---------------- helpers ---------------------------------------------------
__device__ __forceinline__ float lrelu(float x) { return x > 0.f ? x : LEAK * x; }

__device__ __forceinline__ float tanh_a(float x) {
    float r; asm("tanh.approx.f32 %0, %1;" : "=f"(r) : "f"(x)); return r;
}
// exact identity: sigmoid(x) = (1 + tanh(x/2)) / 2
__device__ __forceinline__ float sigm(float x) {
    return fmaf(0.5f, tanh_a(0.5f * x), 0.5f);
}

// ---- packed f32x2 ops (sm_103a dual-FMA pipe) ------------------------------
__device__ __forceinline__ u64 pack2(float a, float b) {
    u64 r; asm("mov.b64 %0, {%1, %2};" : "=l"(r) : "f"(a), "f"(b)); return r;
}
__device__ __forceinline__ void unpack2(float& a, float& b, u64 v) {
    asm("mov.b64 {%0, %1}, %2;" : "=f"(a), "=f"(b) : "l"(v));
}
__device__ __forceinline__ void fma2(u64& d, u64 a, u64 b) {
    asm("fma.rn.f32x2 %0, %1, %2, %0;" : "+l"(d) : "l"(a), "l"(b));
}

// fused conv(K=5)+pool3(pad1)+lrelu for TWO output channels (packed) at
// pooled index j. wp: packed weights [CIN*5] = {w_coA, w_coB}; bb = packed bias.
template<int CIN, int STRIDE, int VALIDL, int MAXI>
__device__ __forceinline__ void conv_pool2(const float* __restrict__ xs,
                                           const u64* __restrict__ wp,
                                           u64 bb, int j, int last,
                                           float& ra, float& rb)
{
    const int c0 = 3 * j - 1;
    u64 S0 = bb, S1 = bb, S2 = bb;
    if (j > 0 && j < last) {                // interior: unconditional
        #pragma unroll
        for (int ci = 0; ci < CIN; ci++) {
            u64 xx[7];
            #pragma unroll
            for (int i = 0; i < 7; i++) {
                const float v = xs[ci * STRIDE + c0 + i];
                xx[i] = pack2(v, v);
            }
            #pragma unroll
            for (int k = 0; k < 5; k++) {
                const u64 w = wp[ci * 5 + k];
                fma2(S0, xx[k],     w);
                fma2(S1, xx[k + 1], w);
                fma2(S2, xx[k + 2], w);
            }
        }
        float a0, b0, a1, b1, a2, b2;
        unpack2(a0, b0, S0); unpack2(a1, b1, S1); unpack2(a2, b2, S2);
        ra = lrelu(fmaxf(fmaxf(a0, a1), a2));
        rb = lrelu(fmaxf(fmaxf(b0, b1), b2));
    } else {                                 // edges: clamped + gated
        #pragma unroll
        for (int ci = 0; ci < CIN; ci++) {
            u64 xx[7];
            #pragma unroll
            for (int i = 0; i < 7; i++) {
                int idx = c0 + i;
                idx = idx < 0 ? 0 : (idx > MAXI ? MAXI : idx);
                const float v = xs[ci * STRIDE + idx];
                xx[i] = pack2(v, v);
            }
            #pragma unroll
            for (int k = 0; k < 5; k++) {
                const u64 w = wp[ci * 5 + k];
                fma2(S0, xx[k],     w);
                fma2(S1, xx[k + 1], w);
                fma2(S2, xx[k + 2], w);
            }
        }
        float a0, b0, a1, b1, a2, b2;
        unpack2(a0, b0, S0); unpack2(a1, b1, S1); unpack2(a2, b2, S2);
        float ma = a1, mb = b1;              // center always valid
        if (c0 >= 0)         { ma = fmaxf(ma, a0); mb = fmaxf(mb, b0); }
        if (c0 + 2 < VALIDL) { ma = fmaxf(ma, a2); mb = fmaxf(mb, b2); }
        ra = lrelu(ma); rb = lrelu(mb);
    }
}

// ---------------- stage 1: conv+lrelu+pool x3, one block per sequence -------
__global__ __launch_bounds__(192) void conv_stage(
    const float* __restrict__ din,
    const float* __restrict__ W1, const float* __restrict__ B1,
    const float* __restrict__ W2, const float* __restrict__ B2,
    const float* __restrict__ W3, const float* __restrict__ B3)
{
    __shared__ float xs[3 * 512];
    __shared__ float p1[10 * 170];
    __shared__ float p2[5 * 56];
    __shared__ float w1s[150]; __shared__ float b1s[10];
    __shared__ float w2s[250]; __shared__ float b2s[5];
    __shared__ float w3s[250]; __shared__ float b3s[10];

    const int tid = threadIdx.x;
    const int b   = blockIdx.x;

    const float* xin = din + (size_t)b * 1536;
    for (int i = tid; i < 1536; i += 192) xs[(i % 3) * 512 + i / 3] = xin[i];
    if (tid < 150) w1s[tid] = W1[tid];
    if (tid < 10)  b1s[tid] = B1[tid];
    for (int i = tid; i < 250; i += 192) w2s[i] = W2[i];
    if (tid < 5)   b2s[tid] = B2[tid];
    for (int i = tid; i < 250; i += 192) w3s[i] = W3[i];
    if (tid < 10)  b3s[tid] = B3[tid];
    __syncthreads();

    // conv1: Cin=3, L=508 -> p1[10][170]; 5 channel-pairs x 32 j-lanes
    if (tid < 160) {
        const int pr = tid >> 5, jb = tid & 31;
        const int co0 = pr * 2, co1 = co0 + 1;
        u64 wp[15];
        #pragma unroll
        for (int i = 0; i < 15; i++)
            wp[i] = pack2(w1s[co0 * 15 + i], w1s[co1 * 15 + i]);
        const u64 bb = pack2(b1s[co0], b1s[co1]);
        for (int j = jb; j < 170; j += 32) {
            float ra, rb;
            conv_pool2<3, 512, 508, 511>(xs, wp, bb, j, 169, ra, rb);
            p1[co0 * 170 + j] = ra;
            p1[co1 * 170 + j] = rb;
        }
    }
    __syncthreads();

    // conv2: Cin=10, L=166 -> p2[5][56]; 3 channel-pairs (last self-dup) x 56 j
    if (tid < 168) {
        const int g = tid / 56, j = tid % 56;
        const int co0 = g * 2;
        const int co1 = (g < 2) ? co0 + 1 : co0;   // pair 2 = {4,4} dup
        u64 wp[50];
        #pragma unroll
        for (int i = 0; i < 50; i++)
            wp[i] = pack2(w2s[co0 * 50 + i], w2s[co1 * 50 + i]);
        const u64 bb = pack2(b2s[co0], b2s[co1]);
        float ra, rb;
        conv_pool2<10, 170, 166, 169>(p1, wp, bb, j, 55, ra, rb);
        p2[co0 * 56 + j] = ra;
        if (g < 2) p2[co1 * 56 + j] = rb;
    }
    __syncthreads();

    // conv3: Cin=5, L=52 -> g_seq[b][t][co]; 5 channel-pairs x 18 t
    if (tid < 90) {
        const int pr = tid / 18, t = tid % 18;
        const int co0 = pr * 2, co1 = co0 + 1;
        u64 wp[25];
        #pragma unroll
        for (int i = 0; i < 25; i++)
            wp[i] = pack2(w3s[co0 * 25 + i], w3s[co1 * 25 + i]);
        const u64 bb = pack2(b3s[co0], b3s[co1]);
        float ra, rb;
        conv_pool2<5, 56, 52, 55>(p2, wp, bb, t, 17, ra, rb);
        g_seq[(size_t)b * 180 + t * 10 + co0] = ra;
        g_seq[(size_t)b * 180 + t * 10 + co1] = rb;
    }
}

// ---------------- stage 2: flow LSTM (3 layers, T=18, H=10) -----------------
__global__ __launch_bounds__(320) void flow_lstm(
    const float* __restrict__ Wih, const float* __restrict__ Whh,
    const float* __restrict__ Bv)
{
    __shared__ __align__(16) float buf[32 * 180];
    __shared__ __align__(16) float hs[2][320];

    const int tid = threadIdx.x;
    const int u  = tid >> 5;           // 0..9
    const int bi = tid & 31;           // 0..31
    const int b0 = blockIdx.x * 32;

    for (int i = tid; i < 5760; i += 320) buf[i] = g_seq[(size_t)b0 * 180 + i];

    float acc = 0.f;

    for (int l = 0; l < 3; l++) {
        const float* wihL = Wih + l * 400;
        const float* whhL = Whh + l * 400;
        const float* bbL  = Bv  + l * 40;
        float wx[40], wh[40], bg[4];
        #pragma unroll
        for (int g = 0; g < 4; g++) {
            const int row = g * 10 + u;
            #pragma unroll
            for (int k = 0; k < 10; k++) {
                wx[g * 10 + k] = wihL[row * 10 + k];
                wh[g * 10 + k] = whhL[row * 10 + k];
            }
            bg[g] = bbL[row];
        }
        float c = 0.f, h = 0.f;
        int cur = 0;
        hs[0][bi * 10 + u] = 0.f;
        __syncthreads();

        for (int t = 0; t < 18; t++) {
            if (t > 0) buf[bi * 180 + (t - 1) * 10 + u] = h;  // deferred output
            const float2* xp2 = (const float2*)(buf + bi * 180 + t * 10);
            const float2* hp2 = (const float2*)(&hs[cur][bi * 10]);
            float g0a = bg[0], g1a = bg[1], g2a = bg[2], g3a = bg[3];
            float g0b = 0.f, g1b = 0.f, g2b = 0.f, g3b = 0.f;
            #pragma unroll
            for (int k2 = 0; k2 < 5; k2++) {
                const float2 xv = xp2[k2];
                const float2 hv = hp2[k2];
                g0a += xv.x * wx[2*k2]      + hv.x * wh[2*k2];
                g0b += xv.y * wx[2*k2 + 1]  + hv.y * wh[2*k2 + 1];
                g1a += xv.x * wx[10+2*k2]   + hv.x * wh[10+2*k2];
                g1b += xv.y * wx[11+2*k2]   + hv.y * wh[11+2*k2];
                g2a += xv.x * wx[20+2*k2]   + hv.x * wh[20+2*k2];
                g2b += xv.y * wx[21+2*k2]   + hv.y * wh[21+2*k2];
                g3a += xv.x * wx[30+2*k2]   + hv.x * wh[30+2*k2];
                g3b += xv.y * wx[31+2*k2]   + hv.y * wh[31+2*k2];
            }
            const float gi = sigm(g0a + g0b), gf = sigm(g1a + g1b);
            const float gg = tanh_a(g2a + g2b), go = sigm(g3a + g3b);
            c = gf * c + gi * gg;
            h = go * tanh_a(c);
            hs[cur ^ 1][bi * 10 + u] = h;
            __syncthreads();
            cur ^= 1;
        }
        buf[bi * 180 + 170 + u] = h;   // slot t=17
        if (l >= 1) acc += h;          // h_n[-1] + h_n[-2]
    }
    g_fv[(size_t)(b0 + bi) * 10 + u] = acc;
}

// ---------------- stage 3: trace LSTM — one warp per trace ------------------
// lane = u + 16*half (u<10). halves split the k-dim; ONE shfl_xor(16) per gate
// combines them, after which every lane owns full gate sums -> no broadcasts.
// x-part of step t+1 is precomputed inside step t's h-dependency window.
__global__ __launch_bounds__(32) void trace_lstm(
    const float* __restrict__ Wih, const float* __restrict__ Whh,
    const float* __restrict__ Bv)
{
    __shared__ __align__(16) float bufA[640];
    __shared__ __align__(16) float bufB[640];

    const int lane = threadIdx.x;
    const int b    = blockIdx.x;
    const int half = lane >> 4;
    const int u    = (lane & 15) % 10;     // lanes 10-15/26-31 duplicate units

    for (int i = lane; i < 640; i += 32) bufA[i] = g_fv[(size_t)b * 640 + i];
    __syncwarp();

    float acc = 0.f;
    float* inb  = bufA;
    float* outb = bufB;

    for (int l = 0; l < 3; l++) {
        const float* wihL = Wih + l * 400;
        const float* whhL = Whh + l * 400;
        const float* bbL  = Bv  + l * 40;
        float wx[4][5], wh[4][5], bg[4];
        #pragma unroll
        for (int g = 0; g < 4; g++) {
            const int row = g * 10 + u;
            #pragma unroll
            for (int j = 0; j < 5; j++) {
                wx[g][j] = wihL[row * 10 + half * 5 + j];
                wh[g][j] = whhL[row * 10 + half * 5 + j];
            }
            bg[g] = (half == 0) ? bbL[row] : 0.f;
        }
        float c = 0.f, h = 0.f;

        // prologue: x-part for t=0
        float xg0, xg1, xg2, xg3;
        {
            const float* xp = inb + half * 5;
            xg0 = bg[0]; xg1 = bg[1]; xg2 = bg[2]; xg3 = bg[3];
            #pragma unroll
            for (int j = 0; j < 5; j++) {
                const float xv = xp[j];
                xg0 += xv * wx[0][j]; xg1 += xv * wx[1][j];
                xg2 += xv * wx[2][j]; xg3 += xv * wx[3][j];
            }
        }

        for (int t = 0; t < 64; t++) {
            float p0 = xg0, p1 = xg1, p2 = xg2, p3 = xg3;
            #pragma unroll
            for (int j = 0; j < 5; j++) {
                const float hv = __shfl_sync(0xFFFFFFFFu, h, half * 5 + j);
                p0 += hv * wh[0][j]; p1 += hv * wh[1][j];
                p2 += hv * wh[2][j]; p3 += hv * wh[3][j];
            }
            // prefetch next x-part (independent of h chain)
            if (t + 1 < 64) {
                const float* xp = inb + (t + 1) * 10 + half * 5;
                xg0 = bg[0]; xg1 = bg[1]; xg2 = bg[2]; xg3 = bg[3];
                #pragma unroll
                for (int j = 0; j < 5; j++) {
                    const float xv = xp[j];
                    xg0 += xv * wx[0][j]; xg1 += xv * wx[1][j];
                    xg2 += xv * wx[2][j]; xg3 += xv * wx[3][j];
                }
            }
            // combine k-halves: every lane gets full gate sums
            p0 += __shfl_xor_sync(0xFFFFFFFFu, p0, 16);
            p1 += __shfl_xor_sync(0xFFFFFFFFu, p1, 16);
            p2 += __shfl_xor_sync(0xFFFFFFFFu, p2, 16);
            p3 += __shfl_xor_sync(0xFFFFFFFFu, p3, 16);
            const float gi = sigm(p0), gf = sigm(p1);
            const float gg = tanh_a(p2), go = sigm(p3);
            c = gf * c + gi * gg;
            h = go * tanh_a(c);
            if (lane < 10) outb[t * 10 + u] = h;
        }
        __syncwarp();
        if (l >= 1) acc += h;
        float* tmp = inb; inb = outb; outb = tmp;
    }
    if (lane < 10) g_tv[(size_t)b * 10 + u] = acc;
}

// ---------------- stage 4: MLP head — float4 loads + k-split + shfl reduce --
__global__ __launch_bounds__(512) void mlp_kernel(
    const float* __restrict__ L1W, const float* __restrict__ L1b,
    const float* __restrict__ L2W, const float* __restrict__ L2b,
    const float* __restrict__ L3W, const float* __restrict__ L3b,
    const float* __restrict__ L4W, const float* __restrict__ L4b,
    float* __restrict__ out)
{
    __shared__ __align__(16) float x0[16];
    __shared__ __align__(16) float h1[128];
    __shared__ __align__(16) float h2[256];
    __shared__ __align__(16) float h3[64];

    const int t   = blockIdx.x;
    const int tid = threadIdx.x;

    if (tid < 10) x0[tid] = g_tv[t * 10 + tid];
    __syncthreads();

    if (tid < 128) {
        float s = L1b[tid];
        #pragma unroll
        for (int k = 0; k < 10; k++) s += x0[k] * L1W[tid * 10 + k];
        h1[tid] = lrelu(s);
    }
    __syncthreads();

    // L2: 256 outputs, 2-way k-split
    {
        const int o = tid >> 1, p = tid & 1;
        const float4* wp = (const float4*)(L2W + o * 128 + p * 64);
        const float4* hp = (const float4*)(h1 + p * 64);
        float sa = 0.f, sb = 0.f;
        #pragma unroll
        for (int i = 0; i < 16; i += 2) {
            const float4 w0 = wp[i],   v0 = hp[i];
            const float4 w1 = wp[i+1], v1 = hp[i+1];
            sa += w0.x*v0.x + w0.y*v0.y + w0.z*v0.z + w0.w*v0.w;
            sb += w1.x*v1.x + w1.y*v1.y + w1.z*v1.z + w1.w*v1.w;
        }
        float s = sa + sb;
        s += __shfl_xor_sync(0xFFFFFFFFu, s, 1);
        if (p == 0) h2[o] = lrelu(s + L2b[o]);
    }
    __syncthreads();

    // L3: 64 outputs, 8-way k-split
    {
        const int o = tid >> 3, p = tid & 7;
        const float4* wp = (const float4*)(L3W + o * 256 + p * 32);
        const float4* hp = (const float4*)(h2 + p * 32);
        float sa = 0.f, sb = 0.f;
        #pragma unroll
        for (int i = 0; i < 8; i += 2) {
            const float4 w0 = wp[i],   v0 = hp[i];
            const float4 w1 = wp[i+1], v1 = hp[i+1];
            sa += w0.x*v0.x + w0.y*v0.y + w0.z*v0.z + w0.w*v0.w;
            sb += w1.x*v1.x + w1.y*v1.y + w1.z*v1.z + w1.w*v1.w;
        }
        float s = sa + sb;
        s += __shfl_xor_sync(0xFFFFFFFFu, s, 4);
        s += __shfl_xor_sync(0xFFFFFFFFu, s, 2);
        s += __shfl_xor_sync(0xFFFFFFFFu, s, 1);
        if (p == 0) h3[o] = lrelu(s + L3b[o]);
    }
    __syncthreads();

    // L4: 7 outputs, warp per output
    {
        const int w = tid >> 5, lane = tid & 31;
        if (w < 7) {
            float s = h3[lane] * L4W[w * 64 + lane]
                    + h3[lane + 32] * L4W[w * 64 + lane + 32];
            s += __shfl_xor_sync(0xFFFFFFFFu, s, 16);
            s += __shfl_xor_sync(0xFFFFFFFFu, s, 8);
            s += __shfl_xor_sync(0xFFFFFFFFu, s, 4);
            s += __shfl_xor_sync(0xFFFFFFFFu, s, 2);
            s += __shfl_xor_sync(0xFFFFFFFFu, s, 1);
            if (lane == 0) out[t * 7 + w] = s + L4b[w];
        }
    }
}

// ---------------- launch ----------------------------------------------------
extern "C" void kernel_launch(void* const* d_in, const int* in_sizes, int n_in,
                              void* d_out, int out_size)
{
    const float* din  = (const float*)d_in[0];
    const float* W1   = (const float*)d_in[1];
    const float* b1   = (const float*)d_in[2];
    const float* W2   = (const float*)d_in[3];
    const float* b2   = (const float*)d_in[4];
    const float* W3   = (const float*)d_in[5];
    const float* b3   = (const float*)d_in[6];
    const float* fWih = (const float*)d_in[7];
    const float* fWhh = (const float*)d_in[8];
    const float* fb   = (const float*)d_in[9];
    const float* tWih = (const float*)d_in[10];
    const float* tWhh = (const float*)d_in[11];
    const float* tb   = (const float*)d_in[12];
    const float* L1W  = (const float*)d_in[13];
    const float* L1b  = (const float*)d_in[14];
    const float* L2W  = (const float*)d_in[15];
    const float* L2b  = (const float*)d_in[16];
    const float* L3W  = (const float*)d_in[17];
    const float* L3b  = (const float*)d_in[18];
    const float* L4W  = (const float*)d_in[19];
    const float* L4b  = (const float*)d_in[20];

    conv_stage<<<4096, 192>>>(din, W1, b1, W2, b2, W3, b3);
    flow_lstm <<<128, 320>>>(fWih, fWhh, fb);
    trace_lstm<<<64, 32>>>(tWih, tWhh, tb);
    mlp_kernel<<<64, 512>>>(L1W, L1b, L2W, L2b, L3W, L3b, L4W, L4b,
                            (float*)d_out);
}

// round 4
// speedup vs baseline: 1.4454x; 1.2937x over previous
#include <cuda_runtime.h>
#include <math.h>

#define LEAK 0.01f
typedef unsigned long long u64;

// ---------------- scratch (device global; no allocation allowed) ------------
__device__ float g_fv[4096 * 10];     // [B, 10] flow vectors = [64,64,10]

// ---------------- helpers ---------------------------------------------------
__device__ __forceinline__ float lrelu(float x) { return x > 0.f ? x : LEAK * x; }

__device__ __forceinline__ float tanh_a(float x) {
    float r; asm("tanh.approx.f32 %0, %1;" : "=f"(r) : "f"(x)); return r;
}
// sigmoid(x) = (1 + tanh(x/2)) / 2
__device__ __forceinline__ float sigm(float x) {
    return fmaf(0.5f, tanh_a(0.5f * x), 0.5f);
}

// ---- packed f32x2 ops ------------------------------------------------------
__device__ __forceinline__ u64 pack2(float a, float b) {
    u64 r; asm("mov.b64 %0, {%1, %2};" : "=l"(r) : "f"(a), "f"(b)); return r;
}
__device__ __forceinline__ void unpack2(float& a, float& b, u64 v) {
    asm("mov.b64 {%0, %1}, %2;" : "=f"(a), "=f"(b) : "l"(v));
}
__device__ __forceinline__ void fma2(u64& d, u64 a, u64 b) {
    asm("fma.rn.f32x2 %0, %1, %2, %0;" : "+l"(d) : "l"(a), "l"(b));
}

// branch-free fused conv(K=5)+pool3(pad1)+lrelu for a packed channel pair.
// xs points one past a zero guard (index -1 valid & zero); rows padded w/ zeros.
template<int CIN, int STRIDE, int VALIDL>
__device__ __forceinline__ void conv_pool2(const float* __restrict__ xs,
                                           const u64* __restrict__ wp,
                                           u64 bb, int j,
                                           float& ra, float& rb)
{
    const int c0 = 3 * j - 1;
    u64 S0 = bb, S1 = bb, S2 = bb;
    #pragma unroll
    for (int ci = 0; ci < CIN; ci++) {
        u64 w[5];
        #pragma unroll
        for (int k = 0; k < 5; k++) w[k] = wp[ci * 5 + k];
        u64 xx[7];
        #pragma unroll
        for (int i = 0; i < 7; i++) {
            const float v = xs[ci * STRIDE + c0 + i];
            xx[i] = pack2(v, v);
        }
        #pragma unroll
        for (int k = 0; k < 5; k++) {
            fma2(S0, xx[k],     w[k]);
            fma2(S1, xx[k + 1], w[k]);
            fma2(S2, xx[k + 2], w[k]);
        }
    }
    float a0, b0, a1, b1, a2, b2;
    unpack2(a0, b0, S0); unpack2(a1, b1, S1); unpack2(a2, b2, S2);
    float ma = a1, mb = b1;                    // center (l=3j) always valid
    if (j > 0)              { ma = fmaxf(ma, a0); mb = fmaxf(mb, b0); }
    if (3 * j + 1 < VALIDL) { ma = fmaxf(ma, a2); mb = fmaxf(mb, b2); }
    ra = lrelu(ma); rb = lrelu(mb);
}

// ============================================================================
// K1: conv x3 (warps 0-4, +part of 5) then flow LSTM (warp 5), 1 block / seq
// ============================================================================
__global__ __launch_bounds__(192) void conv_flow(
    const float* __restrict__ din,
    const float* __restrict__ W1, const float* __restrict__ B1,
    const float* __restrict__ W2, const float* __restrict__ B2,
    const float* __restrict__ W3, const float* __restrict__ B3,
    const float* __restrict__ Wih, const float* __restrict__ Whh,
    const float* __restrict__ Bv)
{
    __shared__ float xs_raw[3 * 520 + 4];     // stride 520, +1 front guard
    __shared__ float p1_raw[10 * 176 + 4];    // stride 176
    __shared__ float p2_raw[5 * 64 + 4];      // stride 64
    __shared__ u64  w1p[75];  __shared__ u64 b1p[5];
    __shared__ u64  w2p[150]; __shared__ u64 b2p[3];
    __shared__ u64  w3p[125]; __shared__ u64 b3p[5];
    __shared__ float seqA[184];
    __shared__ float seqB[184];

    float* xs = xs_raw + 1;
    float* p1 = p1_raw + 1;
    float* p2 = p2_raw + 1;

    const int tid = threadIdx.x;
    const int b   = blockIdx.x;

    // ---- fill phase --------------------------------------------------------
    const float* xin = din + (size_t)b * 1536;
    for (int i = tid; i < 1536; i += 192) xs[(i % 3) * 520 + i / 3] = xin[i];
    // zero guards + row pads
    if (tid == 190) { xs_raw[0] = 0.f; p1_raw[0] = 0.f; p2_raw[0] = 0.f; }
    for (int i = tid; i < 24; i += 192) xs[(i / 8) * 520 + 512 + (i % 8)] = 0.f;
    for (int i = tid; i < 60; i += 192) p1[(i / 6) * 176 + 170 + (i % 6)] = 0.f;
    for (int i = tid; i < 40; i += 192) p2[(i / 8) * 64  + 56  + (i % 8)] = 0.f;
    // packed weights
    for (int i = tid; i < 75; i += 192) {
        const int pr = i / 15, k = i % 15;
        w1p[i] = pack2(W1[(2 * pr) * 15 + k], W1[(2 * pr + 1) * 15 + k]);
    }
    for (int i = tid; i < 150; i += 192) {
        const int g = i / 50, k = i % 50;
        const int co0 = 2 * g, co1 = (co0 + 1 < 5) ? co0 + 1 : co0;
        w2p[i] = pack2(W2[co0 * 50 + k], W2[co1 * 50 + k]);
    }
    for (int i = tid; i < 125; i += 192) {
        const int pr = i / 25, k = i % 25;
        w3p[i] = pack2(W3[(2 * pr) * 25 + k], W3[(2 * pr + 1) * 25 + k]);
    }
    if (tid < 5) b1p[tid] = pack2(B1[2 * tid], B1[2 * tid + 1]);
    if (tid < 3) b2p[tid] = pack2(B2[2 * tid], B2[(2 * tid + 1 < 5) ? 2 * tid + 1 : 2 * tid]);
    if (tid < 5) b3p[tid] = pack2(B3[2 * tid], B3[2 * tid + 1]);
    __syncthreads();

    // ---- LSTM weight prefetch (warp 5, idle during conv1) ------------------
    const int lane = tid - 160;                   // valid for warp 5
    const int lhalf = (lane >= 0) ? (lane >> 4) : 0;
    const int lu    = (lane >= 0) ? ((lane & 15) % 10) : 0;
    float wx[4][5], wh[4][5], bg[4];

    // ---- conv1: 5 pairs x 32 lanes over 170 j ------------------------------
    if (tid < 160) {
        const int pr = tid >> 5, jb = tid & 31;
        const u64* wp = w1p + pr * 15;
        const u64  bb = b1p[pr];
        for (int j = jb; j < 170; j += 32) {
            float ra, rb;
            conv_pool2<3, 520, 508>(xs, wp, bb, j, ra, rb);
            p1[(2 * pr) * 176 + j]     = ra;
            p1[(2 * pr + 1) * 176 + j] = rb;
        }
    } else {
        // prefetch layer-0 LSTM weights
        #pragma unroll
        for (int g = 0; g < 4; g++) {
            const int row = g * 10 + lu;
            #pragma unroll
            for (int k = 0; k < 5; k++) {
                wx[g][k] = Wih[row * 10 + lhalf * 5 + k];
                wh[g][k] = Whh[row * 10 + lhalf * 5 + k];
            }
            bg[g] = (lhalf == 0) ? Bv[row] : 0.f;
        }
    }
    __syncthreads();

    // ---- conv2: tasks 0..167 = (g=task/56, j=task%56); warp5 skips ---------
    if (tid < 160) {
        int task = tid;
        for (int rep = 0; rep < 2; rep++) {
            if (rep == 1) {
                if (tid < 152 || tid >= 160) break;
                task = tid + 8;                 // tasks 160..167
            }
            const int g = task / 56, j = task % 56;
            const int co0 = 2 * g;
            float ra, rb;
            conv_pool2<10, 176, 166>(p1, w2p + g * 50, b2p[g], j, ra, rb);
            p2[co0 * 64 + j] = ra;
            if (g < 2) p2[(co0 + 1) * 64 + j] = rb;
        }
    }
    __syncthreads();

    // ---- conv3: 5 pairs x 18 t -> seqA[t*10+co] ----------------------------
    if (tid < 90) {
        const int pr = tid / 18, t = tid % 18;
        float ra, rb;
        conv_pool2<5, 64, 52>(p2, w3p + pr * 25, b3p[pr], t, ra, rb);
        seqA[t * 10 + 2 * pr]     = ra;
        seqA[t * 10 + 2 * pr + 1] = rb;
    }
    __syncthreads();

    if (tid < 160) return;                       // conv warps done

    // ---- flow LSTM: warp 5, 3 layers, T=18, shfl-based, no barriers --------
    float acc = 0.f;
    for (int l = 0; l < 3; l++) {
        if (l > 0) {
            const float* wihL = Wih + l * 400;
            const float* whhL = Whh + l * 400;
            const float* bbL  = Bv  + l * 40;
            #pragma unroll
            for (int g = 0; g < 4; g++) {
                const int row = g * 10 + lu;
                #pragma unroll
                for (int k = 0; k < 5; k++) {
                    wx[g][k] = wihL[row * 10 + lhalf * 5 + k];
                    wh[g][k] = whhL[row * 10 + lhalf * 5 + k];
                }
                bg[g] = (lhalf == 0) ? bbL[row] : 0.f;
            }
        }
        const float* inb = (l == 1) ? seqB : seqA;
        float* outb      = (l == 0) ? seqB : seqA;   // l==2: unused
        float c = 0.f, h = 0.f;

        float xg0, xg1, xg2, xg3;
        {
            const float* xp = inb + lhalf * 5;
            xg0 = bg[0]; xg1 = bg[1]; xg2 = bg[2]; xg3 = bg[3];
            #pragma unroll
            for (int k = 0; k < 5; k++) {
                const float xv = xp[k];
                xg0 += xv * wx[0][k]; xg1 += xv * wx[1][k];
                xg2 += xv * wx[2][k]; xg3 += xv * wx[3][k];
            }
        }
        for (int t = 0; t < 18; t++) {
            float q0 = xg0, q1 = xg1, q2 = xg2, q3 = xg3;
            #pragma unroll
            for (int k = 0; k < 5; k++) {
                const float hv = __shfl_sync(0xFFFFFFFFu, h, lhalf * 5 + k);
                q0 += hv * wh[0][k]; q1 += hv * wh[1][k];
                q2 += hv * wh[2][k]; q3 += hv * wh[3][k];
            }
            if (t + 1 < 18) {
                const float* xp = inb + (t + 1) * 10 + lhalf * 5;
                xg0 = bg[0]; xg1 = bg[1]; xg2 = bg[2]; xg3 = bg[3];
                #pragma unroll
                for (int k = 0; k < 5; k++) {
                    const float xv = xp[k];
                    xg0 += xv * wx[0][k]; xg1 += xv * wx[1][k];
                    xg2 += xv * wx[2][k]; xg3 += xv * wx[3][k];
                }
            }
            q0 += __shfl_xor_sync(0xFFFFFFFFu, q0, 16);
            q1 += __shfl_xor_sync(0xFFFFFFFFu, q1, 16);
            q2 += __shfl_xor_sync(0xFFFFFFFFu, q2, 16);
            q3 += __shfl_xor_sync(0xFFFFFFFFu, q3, 16);
            const float gi = sigm(q0), gf = sigm(q1);
            const float gg = tanh_a(q2), go = sigm(q3);
            c = gf * c + gi * gg;
            h = go * tanh_a(c);
            if (l < 2 && lane < 10) outb[t * 10 + lu] = h;
            __syncwarp();
        }
        if (l >= 1) acc += h;                    // h_n[-1] + h_n[-2]
    }
    if (lane < 10) g_fv[(size_t)b * 10 + lu] = acc;
}

// ============================================================================
// K2: trace LSTM wavefront (3 warps = 3 layers, skew 1) + fused MLP head
// ============================================================================
__global__ __launch_bounds__(96) void trace_mlp(
    const float* __restrict__ Wih, const float* __restrict__ Whh,
    const float* __restrict__ Bv,
    const float* __restrict__ L1W, const float* __restrict__ L1b,
    const float* __restrict__ L2W, const float* __restrict__ L2b,
    const float* __restrict__ L3W, const float* __restrict__ L3b,
    const float* __restrict__ L4W, const float* __restrict__ L4b,
    float* __restrict__ out)
{
    __shared__ float fvb[640];        // layer-0 input
    __shared__ float sb0[640];        // layer-0 output
    __shared__ float sb1[640];        // layer-1 output
    __shared__ float tsum[2][10];
    __shared__ __align__(16) float tv[12];
    __shared__ __align__(16) float h1[128];
    __shared__ __align__(16) float h2[256];
    __shared__ __align__(16) float h3[64];

    const int tid  = threadIdx.x;
    const int wid  = tid >> 5;        // 0..2 = layer
    const int lane = tid & 31;
    const int half = lane >> 4;
    const int u    = (lane & 15) % 10;
    const int bt   = blockIdx.x;      // trace index t

    for (int i = tid; i < 640; i += 96) fvb[i] = g_fv[(size_t)bt * 640 + i];

    // per-warp layer weights
    float wx[4][5], wh[4][5], bg[4];
    {
        const float* wihL = Wih + wid * 400;
        const float* whhL = Whh + wid * 400;
        const float* bbL  = Bv  + wid * 40;
        #pragma unroll
        for (int g = 0; g < 4; g++) {
            const int row = g * 10 + u;
            #pragma unroll
            for (int k = 0; k < 5; k++) {
                wx[g][k] = wihL[row * 10 + half * 5 + k];
                wh[g][k] = whhL[row * 10 + half * 5 + k];
            }
            bg[g] = (half == 0) ? bbL[row] : 0.f;
        }
    }
    __syncthreads();

    const float* inb = (wid == 0) ? fvb : (wid == 1) ? sb0 : sb1;
    float* outb      = (wid == 0) ? sb0 : sb1;       // wid==2 unused
    float c = 0.f, h = 0.f;

    for (int s = 0; s < 66; s++) {
        const int t = s - wid;
        if (t >= 0 && t < 64) {
            const float* xp = inb + t * 10 + half * 5;
            float q0 = bg[0], q1 = bg[1], q2 = bg[2], q3 = bg[3];
            #pragma unroll
            for (int k = 0; k < 5; k++) {
                const float xv = xp[k];
                q0 += xv * wx[0][k]; q1 += xv * wx[1][k];
                q2 += xv * wx[2][k]; q3 += xv * wx[3][k];
            }
            #pragma unroll
            for (int k = 0; k < 5; k++) {
                const float hv = __shfl_sync(0xFFFFFFFFu, h, half * 5 + k);
                q0 += hv * wh[0][k]; q1 += hv * wh[1][k];
                q2 += hv * wh[2][k]; q3 += hv * wh[3][k];
            }
            q0 += __shfl_xor_sync(0xFFFFFFFFu, q0, 16);
            q1 += __shfl_xor_sync(0xFFFFFFFFu, q1, 16);
            q2 += __shfl_xor_sync(0xFFFFFFFFu, q2, 16);
            q3 += __shfl_xor_sync(0xFFFFFFFFu, q3, 16);
            const float gi = sigm(q0), gf = sigm(q1);
            const float gg = tanh_a(q2), go = sigm(q3);
            c = gf * c + gi * gg;
            h = go * tanh_a(c);
            if (lane < 10) {
                if (wid < 2) outb[t * 10 + u] = h;
                if (t == 63 && wid >= 1) tsum[wid - 1][u] = h;
            }
        }
        __syncthreads();
    }

    if (tid < 10) tv[tid] = tsum[0][tid] + tsum[1][tid];
    __syncthreads();

    // ---- MLP head (96 threads) --------------------------------------------
    for (int o = tid; o < 128; o += 96) {
        float s = L1b[o];
        #pragma unroll
        for (int k = 0; k < 10; k++) s += tv[k] * L1W[o * 10 + k];
        h1[o] = lrelu(s);
    }
    __syncthreads();

    for (int o = tid; o < 256; o += 96) {
        const float4* wp = (const float4*)(L2W + o * 128);
        const float4* hp = (const float4*)h1;
        float sa = 0.f, sb = 0.f;
        #pragma unroll
        for (int i = 0; i < 32; i += 2) {
            const float4 w0 = wp[i],   v0 = hp[i];
            const float4 w1 = wp[i+1], v1 = hp[i+1];
            sa += w0.x*v0.x + w0.y*v0.y + w0.z*v0.z + w0.w*v0.w;
            sb += w1.x*v1.x + w1.y*v1.y + w1.z*v1.z + w1.w*v1.w;
        }
        h2[o] = lrelu(sa + sb + L2b[o]);
    }
    __syncthreads();

    if (tid < 64) {
        const float4* wp = (const float4*)(L3W + tid * 256);
        const float4* hp = (const float4*)h2;
        float sa = 0.f, sb = 0.f;
        #pragma unroll
        for (int i = 0; i < 64; i += 2) {
            const float4 w0 = wp[i],   v0 = hp[i];
            const float4 w1 = wp[i+1], v1 = hp[i+1];
            sa += w0.x*v0.x + w0.y*v0.y + w0.z*v0.z + w0.w*v0.w;
            sb += w1.x*v1.x + w1.y*v1.y + w1.z*v1.z + w1.w*v1.w;
        }
        h3[tid] = lrelu(sa + sb + L3b[tid]);
    }
    __syncthreads();

    if (tid < 7) {
        float s = L4b[tid];
        #pragma unroll
        for (int k = 0; k < 64; k++) s += h3[k] * L4W[tid * 64 + k];
        out[bt * 7 + tid] = s;
    }
}

// ---------------- launch ----------------------------------------------------
extern "C" void kernel_launch(void* const* d_in, const int* in_sizes, int n_in,
                              void* d_out, int out_size)
{
    const float* din  = (const float*)d_in[0];
    const float* W1   = (const float*)d_in[1];
    const float* b1   = (const float*)d_in[2];
    const float* W2   = (const float*)d_in[3];
    const float* b2   = (const float*)d_in[4];
    const float* W3   = (const float*)d_in[5];
    const float* b3   = (const float*)d_in[6];
    const float* fWih = (const float*)d_in[7];
    const float* fWhh = (const float*)d_in[8];
    const float* fb   = (const float*)d_in[9];
    const float* tWih = (const float*)d_in[10];
    const float* tWhh = (const float*)d_in[11];
    const float* tb   = (const float*)d_in[12];
    const float* L1W  = (const float*)d_in[13];
    const float* L1b  = (const float*)d_in[14];
    const float* L2W  = (const float*)d_in[15];
    const float* L2b  = (const float*)d_in[16];
    const float* L3W  = (const float*)d_in[17];
    const float* L3b  = (const float*)d_in[18];
    const float* L4W  = (const float*)d_in[19];
    const float* L4b  = (const float*)d_in[20];

    conv_flow<<<4096, 192>>>(din, W1, b1, W2, b2, W3, b3, fWih, fWhh, fb);
    trace_mlp<<<64, 96>>>(tWih, tWhh, tb,
                          L1W, L1b, L2W, L2b, L3W, L3b, L4W, L4b,
                          (float*)d_out);
}